// round 4
// baseline (speedup 1.0000x reference)
#include <cuda_runtime.h>
#include <math.h>

// Problem constants (fixed by the reference)
#define NV 200
#define NE 512
#define NH 512
#define NT 24
#define NB 1024
#define NS 128
#define BIGF 10000.0f

// Scratch (no cudaMalloc allowed)
__device__ float g_Ht[NV * NH];    // relu(emb @ w1^T + b1)   [V,H]
__device__ float g_tab[NV * NT];   // relu(Ht @ w2^T + b2) with +BIG baked into [0][0]
__device__ float g_llh[NB];        // per-batch log-likelihood

// ---------------------------------------------------------------------------
// Kernel 1: hidden table  Ht[v][j] = relu( sum_e emb[v][e]*w1[j][e] + b1[j] )
// grid (H/128, V/VT), block 128. Each thread: one j, VT vocab rows.
// ---------------------------------------------------------------------------
#define VT 8
__global__ void k_hidden(const float* __restrict__ emb,
                         const float* __restrict__ w1,
                         const float* __restrict__ b1) {
    __shared__ float semb[VT][NE];
    const int v0 = blockIdx.y * VT;
    const int j  = blockIdx.x * 128 + threadIdx.x;

    for (int idx = threadIdx.x; idx < VT * NE; idx += 128) {
        int vi = idx / NE, e = idx % NE;
        int v = v0 + vi;
        semb[vi][e] = (v < NV) ? emb[v * NE + e] : 0.0f;
    }
    __syncthreads();

    float acc[VT];
#pragma unroll
    for (int i = 0; i < VT; i++) acc[i] = 0.0f;

    const float* w = w1 + (size_t)j * NE;
#pragma unroll 4
    for (int e = 0; e < NE; e++) {
        float wv = w[e];
#pragma unroll
        for (int i = 0; i < VT; i++) acc[i] = fmaf(wv, semb[i][e], acc[i]);
    }
    float bb = b1[j];
#pragma unroll
    for (int i = 0; i < VT; i++) {
        int v = v0 + i;
        if (v < NV) g_Ht[v * NH + j] = fmaxf(acc[i] + bb, 0.0f);
    }
}

// ---------------------------------------------------------------------------
// Kernel 2: score table  tab[v][t] = relu( sum_j Ht[v][j]*w2[t][j] + b2[t] )
//           with pad emission bonus baked in: tab[0][0] += BIG.
// grid (V), block 768 (24 warps); warp t computes one dot.
// ---------------------------------------------------------------------------
__global__ void k_scores(const float* __restrict__ w2,
                         const float* __restrict__ b2) {
    const int v    = blockIdx.x;
    const int wid  = threadIdx.x >> 5;
    const int lane = threadIdx.x & 31;
    if (wid >= NT) return;

    const float* h = g_Ht + v * NH;
    const float* w = w2 + wid * NH;
    float acc = 0.0f;
    for (int j = lane; j < NH; j += 32) acc = fmaf(h[j], w[j], acc);
#pragma unroll
    for (int o = 16; o; o >>= 1) acc += __shfl_down_sync(0xffffffffu, acc, o);

    if (lane == 0) {
        float sc = fmaxf(acc + b2[wid], 0.0f);
        if (v == 0 && wid == 0) sc += BIGF;   // pad_mask * BIG at column PAD=0
        g_tab[v * NT + wid] = sc;
    }
}

// ---------------------------------------------------------------------------
// Kernel 3: CRF forward + gold-path score. One warp per batch element.
// Lane t (t<24) holds alpha[t] and the transitions column trans[:,t] in regs.
// grid (B/8), block 256 (8 warps). Emission table cached in shared.
// ---------------------------------------------------------------------------
__global__ void k_crf(const int*   __restrict__ seqs,
                      const int*   __restrict__ labs,
                      const float* __restrict__ st,
                      const float* __restrict__ et,
                      const float* __restrict__ trans) {
    __shared__ float stab[NV * NT];
    for (int i = threadIdx.x; i < NV * NT; i += blockDim.x) stab[i] = g_tab[i];
    __syncthreads();

    const int warp = threadIdx.x >> 5;
    const int lane = threadIdx.x & 31;
    const int b    = blockIdx.x * 8 + warp;
    const int* seq = seqs + b * NS;
    const int* lab = labs + b * NS;
    const int  t   = lane;
    const bool act = (t < NT);

    // transitions column for this lane: tcol[p] = trans[p][t]
    float tcol[NT];
#pragma unroll
    for (int p = 0; p < NT; p++) tcol[p] = act ? trans[p * NT + t] : 0.0f;

    // alpha0 = start + emission(s=0)
    float alpha;
    {
        int s0 = seq[0];
        alpha = act ? (st[t] + stab[s0 * NT + t]) : -1e30f;
    }

    // forward scan
    for (int s = 1; s < NS; s++) {
        int sv = seq[s];
        float v[NT];
#pragma unroll
        for (int p = 0; p < NT; p++)
            v[p] = __shfl_sync(0xffffffffu, alpha, p) + tcol[p];
        float m = v[0];
#pragma unroll
        for (int p = 1; p < NT; p++) m = fmaxf(m, v[p]);
        float sum = 0.0f;
#pragma unroll
        for (int p = 0; p < NT; p++) sum += __expf(v[p] - m);
        float emit = act ? stab[sv * NT + t] : 0.0f;
        alpha = m + __logf(sum) + emit;
    }

    // denom = logsumexp_t(alpha + end_trans)
    float val = act ? (alpha + et[t]) : -1e30f;
    float m = val;
#pragma unroll
    for (int o = 16; o; o >>= 1) m = fmaxf(m, __shfl_xor_sync(0xffffffffu, m, o));
    float sum = act ? __expf(val - m) : 0.0f;
#pragma unroll
    for (int o = 16; o; o >>= 1) sum += __shfl_xor_sync(0xffffffffu, sum, o);
    float denom = m + __logf(sum);

    // numerator: gold-path score (lanes stride over s)
    float acc = 0.0f;
    for (int s = lane; s < NS; s += 32) {
        int ls = lab[s];
        acc += stab[seq[s] * NT + ls];          // emission at gold label (BIG baked in)
        if (s + 1 < NS) acc += trans[ls * NT + lab[s + 1]];
    }
#pragma unroll
    for (int o = 16; o; o >>= 1) acc += __shfl_xor_sync(0xffffffffu, acc, o);

    if (lane == 0) {
        float num = acc + st[lab[0]] + et[lab[NS - 1]];
        g_llh[b] = num - denom;
    }
}

// ---------------------------------------------------------------------------
// Kernel 4: deterministic mean-reduce of 1024 llh values, write -mean.
// grid (1), block 512.
// ---------------------------------------------------------------------------
__global__ void k_reduce(float* __restrict__ out) {
    __shared__ float sh[512];
    int tid = threadIdx.x;
    sh[tid] = g_llh[tid] + g_llh[tid + 512];
    __syncthreads();
    for (int off = 256; off > 0; off >>= 1) {
        if (tid < off) sh[tid] += sh[tid + off];
        __syncthreads();
    }
    if (tid == 0) out[0] = -(sh[0] / (float)NB);
}

// ---------------------------------------------------------------------------
extern "C" void kernel_launch(void* const* d_in, const int* in_sizes, int n_in,
                              void* d_out, int out_size) {
    const int*   sequences   = (const int*)  d_in[0];
    const int*   labels      = (const int*)  d_in[1];
    // d_in[2] = true_lengths (unused by the reference forward)
    const float* emb         = (const float*)d_in[3];
    const float* w1          = (const float*)d_in[4];
    const float* b1          = (const float*)d_in[5];
    const float* w2          = (const float*)d_in[6];
    const float* b2          = (const float*)d_in[7];
    const float* start_trans = (const float*)d_in[8];
    const float* end_trans   = (const float*)d_in[9];
    const float* transitions = (const float*)d_in[10];
    float* out = (float*)d_out;

    dim3 g1(NH / 128, (NV + VT - 1) / VT);
    k_hidden<<<g1, 128>>>(emb, w1, b1);
    k_scores<<<NV, NT * 32>>>(w2, b2);
    k_crf<<<NB / 8, 256>>>(sequences, labels, start_trans, end_trans, transitions);
    k_reduce<<<1, 512>>>(out);
}

// round 5
// speedup vs baseline: 1.3388x; 1.3388x over previous
#include <cuda_runtime.h>
#include <math.h>

// Problem constants (fixed by the reference)
#define NV 200
#define NE 512
#define NH 512
#define NT 24
#define NB 1024
#define NS 128
#define BIGF 10000.0f
#define FPSCALE 1048576.0f   // 2^20 fixed-point scale for deterministic reduce

// Scratch (no cudaMalloc allowed)
__device__ float g_Ht[NV * NH];     // relu(emb @ w1^T + b1)   [V,H]
__device__ float g_tab[NV * NT];    // log-domain scores (BIG baked into [0][0])
__device__ float g_etab[NV * NT];   // exp(score - rowmax)
__device__ float g_roff[NV];        // rowmax per vocab row
__device__ unsigned long long g_acc;    // fixed-point llh accumulator (zero-init)
__device__ unsigned int       g_ticket; // last-block ticket (zero-init)

// ---------------------------------------------------------------------------
// Kernel 1: hidden table  Ht[v][j] = relu( sum_e emb[v][e]*w1[j][e] + b1[j] )
// grid (H/128, V/VT), block 128.
// ---------------------------------------------------------------------------
#define VT 8
__global__ void k_hidden(const float* __restrict__ emb,
                         const float* __restrict__ w1,
                         const float* __restrict__ b1) {
    if (blockIdx.x == 0 && blockIdx.y == 0 && threadIdx.x == 0) {
        g_acc = 0ULL;          // reset per graph replay (consumed by k_crf later)
        g_ticket = 0u;
    }
    __shared__ float semb[VT][NE];
    const int v0 = blockIdx.y * VT;
    const int j  = blockIdx.x * 128 + threadIdx.x;

    for (int idx = threadIdx.x; idx < VT * NE; idx += 128) {
        int vi = idx / NE, e = idx % NE;
        int v = v0 + vi;
        semb[vi][e] = (v < NV) ? emb[v * NE + e] : 0.0f;
    }
    __syncthreads();

    float acc[VT];
#pragma unroll
    for (int i = 0; i < VT; i++) acc[i] = 0.0f;

    const float* w = w1 + (size_t)j * NE;
#pragma unroll 4
    for (int e = 0; e < NE; e++) {
        float wv = w[e];
#pragma unroll
        for (int i = 0; i < VT; i++) acc[i] = fmaf(wv, semb[i][e], acc[i]);
    }
    float bb = b1[j];
#pragma unroll
    for (int i = 0; i < VT; i++) {
        int v = v0 + i;
        if (v < NV) g_Ht[v * NH + j] = fmaxf(acc[i] + bb, 0.0f);
    }
}

// ---------------------------------------------------------------------------
// Kernel 2: score table + exp-emission table + row offsets.
// grid (V), block 768 (exactly 24 warps); warp t computes one dot.
// ---------------------------------------------------------------------------
__global__ void k_scores(const float* __restrict__ w2,
                         const float* __restrict__ b2) {
    __shared__ float sS[NT];
    const int v    = blockIdx.x;
    const int wid  = threadIdx.x >> 5;
    const int lane = threadIdx.x & 31;

    {
        const float* h = g_Ht + v * NH;
        const float* w = w2 + wid * NH;
        float acc = 0.0f;
        for (int j = lane; j < NH; j += 32) acc = fmaf(h[j], w[j], acc);
#pragma unroll
        for (int o = 16; o; o >>= 1) acc += __shfl_down_sync(0xffffffffu, acc, o);
        if (lane == 0) {
            float sc = fmaxf(acc + b2[wid], 0.0f);
            if (v == 0 && wid == 0) sc += BIGF;   // pad bonus baked in
            sS[wid] = sc;
        }
    }
    __syncthreads();
    if (threadIdx.x < NT) {
        int tt = threadIdx.x;
        float sc = sS[tt];
        float rm = sS[0];
#pragma unroll
        for (int i = 1; i < NT; i++) rm = fmaxf(rm, sS[i]);
        g_tab[v * NT + tt]  = sc;
        g_etab[v * NT + tt] = __expf(sc - rm);
        if (tt == 0) g_roff[v] = rm;
    }
}

// ---------------------------------------------------------------------------
// Kernel 3: scaled (linear-domain) CRF forward + gold score + fused reduce.
// One warp per batch element; lane t holds p[t] and exp(trans[:,t]) in regs.
// grid (B/8), block 256.
// ---------------------------------------------------------------------------
__global__ void k_crf(const int*   __restrict__ seqs,
                      const int*   __restrict__ labs,
                      const float* __restrict__ st,
                      const float* __restrict__ et,
                      const float* __restrict__ trans,
                      float*       __restrict__ out) {
    __shared__ float stab[NV * NT];     // log scores (numerator lookups)
    __shared__ float setab[NV * NT];    // exp-emission table
    __shared__ float sroff[NV];
    __shared__ float strans[NT * NT];
    __shared__ int   sseq[8][NS];
    __shared__ float sst[NT], set[NT];
    __shared__ float sll[8];

    const int tid = threadIdx.x;
    for (int i = tid; i < NV * NT; i += 256) { stab[i] = g_tab[i]; setab[i] = g_etab[i]; }
    for (int i = tid; i < NV; i += 256) sroff[i] = g_roff[i];
    for (int i = tid; i < NT * NT; i += 256) strans[i] = trans[i];
    if (tid < NT) { sst[tid] = st[tid]; set[tid] = et[tid]; }
    {
        const int base = blockIdx.x * 8 * NS;
        for (int i = tid; i < 8 * NS; i += 256) sseq[0][i] = seqs[base + i];
    }
    __syncthreads();

    const int warp = tid >> 5;
    const int lane = tid & 31;
    const int b    = blockIdx.x * 8 + warp;
    const int* lab = labs + b * NS;
    const int* seq = sseq[warp];
    const int  t   = lane;
    const bool act = (t < NT);

    // exp(transitions) column for this lane (one-time MUFU cost)
    float Ecol[NT];
#pragma unroll
    for (int p = 0; p < NT; p++) Ecol[p] = act ? __expf(strans[p * NT + t]) : 0.0f;

    // numerator (gold path) + row-offset sum, lanes stride over s
    float nacc = 0.0f, racc = 0.0f;
    for (int s = lane; s < NS; s += 32) {
        int sv = seq[s], ls = lab[s];
        nacc += stab[sv * NT + ls];
        racc += sroff[sv];
        if (s + 1 < NS) nacc += strans[ls * NT + lab[s + 1]];
    }
#pragma unroll
    for (int o = 16; o; o >>= 1) {
        nacc += __shfl_xor_sync(0xffffffffu, nacc, o);
        racc += __shfl_xor_sync(0xffffffffu, racc, o);
    }

    // scaled forward scan: p[t] tracks exp(alpha - (roff-sum + c))
    float p = act ? __expf(sst[t]) * setab[seq[0] * NT + t] : 0.0f;
    float c = 0.0f;
    for (int s = 1; s < NS; s++) {
        int sv = seq[s];
        float pv[NT];
#pragma unroll
        for (int i = 0; i < NT; i++) pv[i] = __shfl_sync(0xffffffffu, p, i);
        float a0 = 0.f, a1 = 0.f, a2 = 0.f, a3 = 0.f;
#pragma unroll
        for (int i = 0; i < NT; i += 4) {
            a0 = fmaf(pv[i    ], Ecol[i    ], a0);
            a1 = fmaf(pv[i + 1], Ecol[i + 1], a1);
            a2 = fmaf(pv[i + 2], Ecol[i + 2], a2);
            a3 = fmaf(pv[i + 3], Ecol[i + 3], a3);
        }
        float q = (a0 + a1) + (a2 + a3);
        float e = act ? setab[sv * NT + t] : 0.0f;
        p = q * e;
        if ((s & 7) == 0) {                 // renormalize every 8 steps
            float ssum = 0.0f;
#pragma unroll
            for (int i = 0; i < NT; i++) ssum += pv[i];
            p *= __fdividef(1.0f, ssum);
            c += __logf(ssum);
        }
    }

    // denom = c + sum(roff over tokens) + log( sum_t p[t]*exp(end[t]) )
    float ee = act ? __expf(set[t]) : 0.0f;
    float v = p * ee;
#pragma unroll
    for (int o = 16; o; o >>= 1) v += __shfl_xor_sync(0xffffffffu, v, o);
    float denom = c + racc + __logf(v);

    if (lane == 0) {
        float num = nacc + sst[lab[0]] + set[lab[NS - 1]];
        sll[warp] = num - denom;
    }
    __syncthreads();

    // fused deterministic reduce: int64 fixed-point atomics + last-block write
    if (tid == 0) {
        float bs = 0.0f;
#pragma unroll
        for (int w = 0; w < 8; w++) bs += sll[w];
        long long q = __float2ll_rn(bs * FPSCALE);
        atomicAdd(&g_acc, (unsigned long long)q);
        __threadfence();
        unsigned int done = atomicAdd(&g_ticket, 1u);
        if (done == gridDim.x - 1) {
            unsigned long long tot = atomicAdd(&g_acc, 0ULL);   // safe read
            double mean = (double)(long long)tot / ((double)FPSCALE * (double)NB);
            out[0] = (float)(-mean);
        }
    }
}

// ---------------------------------------------------------------------------
extern "C" void kernel_launch(void* const* d_in, const int* in_sizes, int n_in,
                              void* d_out, int out_size) {
    const int*   sequences   = (const int*)  d_in[0];
    const int*   labels      = (const int*)  d_in[1];
    // d_in[2] = true_lengths (unused by the reference forward)
    const float* emb         = (const float*)d_in[3];
    const float* w1          = (const float*)d_in[4];
    const float* b1          = (const float*)d_in[5];
    const float* w2          = (const float*)d_in[6];
    const float* b2          = (const float*)d_in[7];
    const float* start_trans = (const float*)d_in[8];
    const float* end_trans   = (const float*)d_in[9];
    const float* transitions = (const float*)d_in[10];
    float* out = (float*)d_out;

    dim3 g1(NH / 128, (NV + VT - 1) / VT);
    k_hidden<<<g1, 128>>>(emb, w1, b1);
    k_scores<<<NV, NT * 32>>>(w2, b2);
    k_crf<<<NB / 8, 256>>>(sequences, labels, start_trans, end_trans, transitions, out);
}

// round 10
// speedup vs baseline: 2.3090x; 1.7247x over previous
#include <cuda_runtime.h>
#include <math.h>

// Problem constants (fixed by the reference)
#define NV 200
#define NE 512
#define NH 512
#define NT 24
#define NB 1024
#define NS 128
#define BIGF 10000.0f
#define FPSCALE 1048576.0f   // 2^20 fixed-point scale for deterministic reduce
#define KC 8                 // split-K chunks in k_hidden
#define KCH (NE / KC)        // 64 k per chunk

// Scratch (no cudaMalloc allowed)
__device__ float g_w1t[NE * NH];          // w1 transposed: [e][j]
__device__ float g_part[KC * NV * NH];    // split-K partial sums
__device__ float g_tab[NV * NT];          // log-domain scores (BIG baked into [0][0])
__device__ float g_etab[NV * NT];         // exp(score - rowmax)
__device__ float g_roff[NV];              // rowmax per vocab row
__device__ unsigned long long g_acc;      // fixed-point llh accumulator
__device__ unsigned int       g_ticket;   // last-block ticket

// ---------------------------------------------------------------------------
// Kernel 0: transpose w1 (512x512) -> g_w1t, and reset reduce counters.
// grid (16,16), block (32,8).
// ---------------------------------------------------------------------------
__global__ void k_transpose(const float* __restrict__ w1) {
    if (blockIdx.x == 0 && blockIdx.y == 0 && threadIdx.x == 0 && threadIdx.y == 0) {
        g_acc = 0ULL;
        g_ticket = 0u;
    }
    __shared__ float tile[32][33];
    int x = blockIdx.x * 32 + threadIdx.x;
    int y = blockIdx.y * 32 + threadIdx.y;
#pragma unroll
    for (int i = 0; i < 32; i += 8)
        tile[threadIdx.y + i][threadIdx.x] = w1[(size_t)(y + i) * NE + x];
    __syncthreads();
    x = blockIdx.y * 32 + threadIdx.x;
    y = blockIdx.x * 32 + threadIdx.y;
#pragma unroll
    for (int i = 0; i < 32; i += 8)
        g_w1t[(size_t)(y + i) * NH + x] = tile[threadIdx.x][threadIdx.y + i];
}

// ---------------------------------------------------------------------------
// Kernel 1: split-K hidden GEMM partials.
// grid (NV/8 = 25, KC = 8), block 128. Thread owns 4 j (float4) x 8 v accs.
// Per k-iter: 1 coalesced LDG.128 (w1t) + 2 broadcast LDS.128 (emb) + 32 FFMA.
// ---------------------------------------------------------------------------
__global__ void k_hidden(const float* __restrict__ emb) {
    __shared__ float setb[KCH * 8];   // emb tile transposed: [kk][vi]
    const int tid = threadIdx.x;
    const int v0  = blockIdx.x * 8;
    const int k0  = blockIdx.y * KCH;

    for (int i = tid; i < KCH * 8; i += 128) {
        int vi = i >> 6, kk = i & (KCH - 1);
        setb[kk * 8 + vi] = emb[(size_t)(v0 + vi) * NE + k0 + kk];
    }
    __syncthreads();

    float4 acc[8];
#pragma unroll
    for (int i = 0; i < 8; i++) acc[i] = make_float4(0.f, 0.f, 0.f, 0.f);

    const float4* wp = reinterpret_cast<const float4*>(g_w1t + (size_t)k0 * NH) + tid;
#pragma unroll 4
    for (int kk = 0; kk < KCH; kk++) {
        float4 w  = wp[kk * (NH / 4)];
        float4 e0 = *reinterpret_cast<const float4*>(&setb[kk * 8]);
        float4 e1 = *reinterpret_cast<const float4*>(&setb[kk * 8 + 4]);
        float ev[8] = {e0.x, e0.y, e0.z, e0.w, e1.x, e1.y, e1.z, e1.w};
#pragma unroll
        for (int vi = 0; vi < 8; vi++) {
            acc[vi].x = fmaf(ev[vi], w.x, acc[vi].x);
            acc[vi].y = fmaf(ev[vi], w.y, acc[vi].y);
            acc[vi].z = fmaf(ev[vi], w.z, acc[vi].z);
            acc[vi].w = fmaf(ev[vi], w.w, acc[vi].w);
        }
    }

    float* outp = g_part + (size_t)blockIdx.y * (NV * NH);
#pragma unroll
    for (int vi = 0; vi < 8; vi++)
        reinterpret_cast<float4*>(outp + (size_t)(v0 + vi) * NH)[tid] = acc[vi];
}

// ---------------------------------------------------------------------------
// Kernel 2: combine partials (+b1, relu) into shared, then score table +
// exp-emission table + row offsets. grid (NV), block 768 (24 warps).
// ---------------------------------------------------------------------------
__global__ void k_scores(const float* __restrict__ b1,
                         const float* __restrict__ w2,
                         const float* __restrict__ b2) {
    __shared__ float sh[NH];
    __shared__ float sS[NT];
    const int v   = blockIdx.x;
    const int tid = threadIdx.x;

    if (tid < NH) {
        float s = b1[tid];
#pragma unroll
        for (int p = 0; p < KC; p++) s += g_part[p * (NV * NH) + (size_t)v * NH + tid];
        sh[tid] = fmaxf(s, 0.0f);
    }
    __syncthreads();

    const int wid  = tid >> 5;
    const int lane = tid & 31;
    {
        const float* w = w2 + wid * NH;
        float acc = 0.0f;
        for (int j = lane; j < NH; j += 32) acc = fmaf(sh[j], w[j], acc);
#pragma unroll
        for (int o = 16; o; o >>= 1) acc += __shfl_down_sync(0xffffffffu, acc, o);
        if (lane == 0) {
            float sc = fmaxf(acc + b2[wid], 0.0f);
            if (v == 0 && wid == 0) sc += BIGF;   // pad bonus baked in
            sS[wid] = sc;
        }
    }
    __syncthreads();
    if (tid < NT) {
        int tt = tid;
        float sc = sS[tt];
        float rm = sS[0];
#pragma unroll
        for (int i = 1; i < NT; i++) rm = fmaxf(rm, sS[i]);
        g_tab[v * NT + tt]  = sc;
        g_etab[v * NT + tt] = __expf(sc - rm);
        if (tt == 0) g_roff[v] = rm;
    }
}

// ---------------------------------------------------------------------------
// Kernel 3: scaled (linear-domain) CRF forward + gold score + fused reduce.
// One warp per batch element; lane t holds p[t] and exp(trans[:,t]) in regs.
// grid (B/8), block 256.
// ---------------------------------------------------------------------------
__global__ void k_crf(const int*   __restrict__ seqs,
                      const int*   __restrict__ labs,
                      const float* __restrict__ st,
                      const float* __restrict__ et,
                      const float* __restrict__ trans,
                      float*       __restrict__ out) {
    __shared__ float stab[NV * NT];     // log scores (numerator lookups)
    __shared__ float setab[NV * NT];    // exp-emission table
    __shared__ float sroff[NV];
    __shared__ float strans[NT * NT];
    __shared__ int   sseq[8][NS];
    __shared__ float sst[NT], set[NT];
    __shared__ float sll[8];

    const int tid = threadIdx.x;
    for (int i = tid; i < NV * NT; i += 256) { stab[i] = g_tab[i]; setab[i] = g_etab[i]; }
    for (int i = tid; i < NV; i += 256) sroff[i] = g_roff[i];
    for (int i = tid; i < NT * NT; i += 256) strans[i] = trans[i];
    if (tid < NT) { sst[tid] = st[tid]; set[tid] = et[tid]; }
    {
        const int base = blockIdx.x * 8 * NS;
        for (int i = tid; i < 8 * NS; i += 256) sseq[0][i] = seqs[base + i];
    }
    __syncthreads();

    const int warp = tid >> 5;
    const int lane = tid & 31;
    const int b    = blockIdx.x * 8 + warp;
    const int* lab = labs + b * NS;
    const int* seq = sseq[warp];
    const int  t   = lane;
    const bool act = (t < NT);

    // exp(transitions) column for this lane (one-time MUFU cost)
    float Ecol[NT];
#pragma unroll
    for (int p = 0; p < NT; p++) Ecol[p] = act ? __expf(strans[p * NT + t]) : 0.0f;

    // numerator (gold path) + row-offset sum, lanes stride over s
    float nacc = 0.0f, racc = 0.0f;
    for (int s = lane; s < NS; s += 32) {
        int sv = seq[s], ls = lab[s];
        nacc += stab[sv * NT + ls];
        racc += sroff[sv];
        if (s + 1 < NS) nacc += strans[ls * NT + lab[s + 1]];
    }
#pragma unroll
    for (int o = 16; o; o >>= 1) {
        nacc += __shfl_xor_sync(0xffffffffu, nacc, o);
        racc += __shfl_xor_sync(0xffffffffu, racc, o);
    }

    // scaled forward scan: p[t] tracks exp(alpha - (roff-sum + c))
    float p = act ? __expf(sst[t]) * setab[seq[0] * NT + t] : 0.0f;
    float c = 0.0f;
    for (int s = 1; s < NS; s++) {
        int sv = seq[s];
        float pv[NT];
#pragma unroll
        for (int i = 0; i < NT; i++) pv[i] = __shfl_sync(0xffffffffu, p, i);
        float a0 = 0.f, a1 = 0.f, a2 = 0.f, a3 = 0.f;
#pragma unroll
        for (int i = 0; i < NT; i += 4) {
            a0 = fmaf(pv[i    ], Ecol[i    ], a0);
            a1 = fmaf(pv[i + 1], Ecol[i + 1], a1);
            a2 = fmaf(pv[i + 2], Ecol[i + 2], a2);
            a3 = fmaf(pv[i + 3], Ecol[i + 3], a3);
        }
        float q = (a0 + a1) + (a2 + a3);
        float e = act ? setab[sv * NT + t] : 0.0f;
        p = q * e;
        if ((s & 7) == 0) {                 // renormalize every 8 steps
            float ssum = 0.0f;
#pragma unroll
            for (int i = 0; i < NT; i++) ssum += pv[i];
            p *= __fdividef(1.0f, ssum);
            c += __logf(ssum);
        }
    }

    // denom = c + sum(roff over tokens) + log( sum_t p[t]*exp(end[t]) )
    float ee = act ? __expf(set[t]) : 0.0f;
    float v = p * ee;
#pragma unroll
    for (int o = 16; o; o >>= 1) v += __shfl_xor_sync(0xffffffffu, v, o);
    float denom = c + racc + __logf(v);

    if (lane == 0) {
        float num = nacc + sst[lab[0]] + set[lab[NS - 1]];
        sll[warp] = num - denom;
    }
    __syncthreads();

    // fused deterministic reduce: int64 fixed-point atomics + last-block write
    if (tid == 0) {
        float bs = 0.0f;
#pragma unroll
        for (int w = 0; w < 8; w++) bs += sll[w];
        long long q = __float2ll_rn(bs * FPSCALE);
        atomicAdd(&g_acc, (unsigned long long)q);
        __threadfence();
        unsigned int done = atomicAdd(&g_ticket, 1u);
        if (done == gridDim.x - 1) {
            unsigned long long tot = atomicAdd(&g_acc, 0ULL);   // safe read
            double mean = (double)(long long)tot / ((double)FPSCALE * (double)NB);
            out[0] = (float)(-mean);
        }
    }
}

// ---------------------------------------------------------------------------
extern "C" void kernel_launch(void* const* d_in, const int* in_sizes, int n_in,
                              void* d_out, int out_size) {
    const int*   sequences   = (const int*)  d_in[0];
    const int*   labels      = (const int*)  d_in[1];
    // d_in[2] = true_lengths (unused by the reference forward)
    const float* emb         = (const float*)d_in[3];
    const float* w1          = (const float*)d_in[4];
    const float* b1          = (const float*)d_in[5];
    const float* w2          = (const float*)d_in[6];
    const float* b2          = (const float*)d_in[7];
    const float* start_trans = (const float*)d_in[8];
    const float* end_trans   = (const float*)d_in[9];
    const float* transitions = (const float*)d_in[10];
    float* out = (float*)d_out;

    k_transpose<<<dim3(16, 16), dim3(32, 8)>>>(w1);
    k_hidden<<<dim3(NV / 8, KC), 128>>>(emb);
    k_scores<<<NV, NT * 32>>>(b1, w2, b2);
    k_crf<<<NB / 8, 256>>>(sequences, labels, start_trans, end_trans, transitions, out);
}

// round 13
// speedup vs baseline: 2.6973x; 1.1682x over previous
#include <cuda_runtime.h>
#include <math.h>

// Problem constants (fixed by the reference)
#define NV 200
#define NE 512
#define NH 512
#define NT 24
#define NB 1024
#define NS 128
#define BIGF 10000.0f
#define FPSCALE 1048576.0f   // 2^20 fixed-point scale for deterministic reduce
#define KC 8                 // split-K chunks in k_hidden
#define KCH (NE / KC)        // 64 k per chunk

// Scratch (no cudaMalloc allowed)
__device__ float g_w1t[NE * NH];          // w1 transposed: [e][j]
__device__ float g_part[KC * NV * NH];    // split-K partial sums
__device__ float g_tab[NV * NT];          // log-domain scores (BIG baked into [0][0])
__device__ float g_etab[NV * NT];         // exp(score - rowmax)
__device__ float g_roff[NV];              // rowmax per vocab row
__device__ unsigned long long g_acc;      // fixed-point llh accumulator
__device__ unsigned int       g_ticket;   // last-block ticket

// ---------------------------------------------------------------------------
// Kernel 0: transpose w1 (512x512) -> g_w1t, and reset reduce counters.
// grid (16,16), block (32,8).
// ---------------------------------------------------------------------------
__global__ void k_transpose(const float* __restrict__ w1) {
    if (blockIdx.x == 0 && blockIdx.y == 0 && threadIdx.x == 0 && threadIdx.y == 0) {
        g_acc = 0ULL;
        g_ticket = 0u;
    }
    __shared__ float tile[32][33];
    int x = blockIdx.x * 32 + threadIdx.x;
    int y = blockIdx.y * 32 + threadIdx.y;
#pragma unroll
    for (int i = 0; i < 32; i += 8)
        tile[threadIdx.y + i][threadIdx.x] = w1[(size_t)(y + i) * NE + x];
    __syncthreads();
    x = blockIdx.y * 32 + threadIdx.x;
    y = blockIdx.x * 32 + threadIdx.y;
#pragma unroll
    for (int i = 0; i < 32; i += 8)
        g_w1t[(size_t)(y + i) * NH + x] = tile[threadIdx.x][threadIdx.y + i];
}

// ---------------------------------------------------------------------------
// Kernel 1: split-K hidden GEMM partials.
// grid (NV/8 = 25, KC = 8), block 128. Thread owns 4 j (float4) x 8 v accs.
// ---------------------------------------------------------------------------
__global__ void k_hidden(const float* __restrict__ emb) {
    __shared__ float setb[KCH * 8];   // emb tile transposed: [kk][vi]
    const int tid = threadIdx.x;
    const int v0  = blockIdx.x * 8;
    const int k0  = blockIdx.y * KCH;

    for (int i = tid; i < KCH * 8; i += 128) {
        int vi = i >> 6, kk = i & (KCH - 1);
        setb[kk * 8 + vi] = emb[(size_t)(v0 + vi) * NE + k0 + kk];
    }
    __syncthreads();

    float4 acc[8];
#pragma unroll
    for (int i = 0; i < 8; i++) acc[i] = make_float4(0.f, 0.f, 0.f, 0.f);

    const float4* wp = reinterpret_cast<const float4*>(g_w1t + (size_t)k0 * NH) + tid;
#pragma unroll 4
    for (int kk = 0; kk < KCH; kk++) {
        float4 w  = wp[kk * (NH / 4)];
        float4 e0 = *reinterpret_cast<const float4*>(&setb[kk * 8]);
        float4 e1 = *reinterpret_cast<const float4*>(&setb[kk * 8 + 4]);
        float ev[8] = {e0.x, e0.y, e0.z, e0.w, e1.x, e1.y, e1.z, e1.w};
#pragma unroll
        for (int vi = 0; vi < 8; vi++) {
            acc[vi].x = fmaf(ev[vi], w.x, acc[vi].x);
            acc[vi].y = fmaf(ev[vi], w.y, acc[vi].y);
            acc[vi].z = fmaf(ev[vi], w.z, acc[vi].z);
            acc[vi].w = fmaf(ev[vi], w.w, acc[vi].w);
        }
    }

    float* outp = g_part + (size_t)blockIdx.y * (NV * NH);
#pragma unroll
    for (int vi = 0; vi < 8; vi++)
        reinterpret_cast<float4*>(outp + (size_t)(v0 + vi) * NH)[tid] = acc[vi];
}

// ---------------------------------------------------------------------------
// Kernel 2: combine partials (+b1, relu) into shared, then score table +
// exp-emission table + row offsets. grid (NV), block 768 (24 warps).
// ---------------------------------------------------------------------------
__global__ void k_scores(const float* __restrict__ b1,
                         const float* __restrict__ w2,
                         const float* __restrict__ b2) {
    __shared__ float sh[NH];
    __shared__ float sS[NT];
    const int v   = blockIdx.x;
    const int tid = threadIdx.x;

    if (tid < NH) {
        float s = b1[tid];
#pragma unroll
        for (int p = 0; p < KC; p++) s += g_part[p * (NV * NH) + (size_t)v * NH + tid];
        sh[tid] = fmaxf(s, 0.0f);
    }
    __syncthreads();

    const int wid  = tid >> 5;
    const int lane = tid & 31;
    {
        const float* w = w2 + wid * NH;
        float acc = 0.0f;
        for (int j = lane; j < NH; j += 32) acc = fmaf(sh[j], w[j], acc);
#pragma unroll
        for (int o = 16; o; o >>= 1) acc += __shfl_down_sync(0xffffffffu, acc, o);
        if (lane == 0) {
            float sc = fmaxf(acc + b2[wid], 0.0f);
            if (v == 0 && wid == 0) sc += BIGF;   // pad bonus baked in
            sS[wid] = sc;
        }
    }
    __syncthreads();
    if (tid < NT) {
        int tt = tid;
        float sc = sS[tt];
        float rm = sS[0];
#pragma unroll
        for (int i = 1; i < NT; i++) rm = fmaxf(rm, sS[i]);
        g_tab[v * NT + tt]  = sc;
        g_etab[v * NT + tt] = __expf(sc - rm);
        if (tt == 0) g_roff[v] = rm;
    }
}

// ---------------------------------------------------------------------------
// Kernel 3: scaled (linear-domain) CRF forward + gold score + fused reduce.
// One warp per batch element. Cross-lane alpha broadcast via double-buffered
// SHARED MEMORY (1 STS + 1 syncwarp + 6 broadcast LDS.128 per step) instead
// of 24 SHFLs -> relieves the MIO shuffle pipe that bound the scan.
// grid (B/8), block 256.
// ---------------------------------------------------------------------------
__global__ void k_crf(const int*   __restrict__ seqs,
                      const int*   __restrict__ labs,
                      const float* __restrict__ st,
                      const float* __restrict__ et,
                      const float* __restrict__ trans,
                      float*       __restrict__ out) {
    __shared__ float stab[NV * NT];     // log scores (numerator lookups)
    __shared__ float setab[NV * NT];    // exp-emission table
    __shared__ float sroff[NV];
    __shared__ float strans[NT * NT];
    __shared__ int   sseq[8][NS];
    __shared__ float sst[NT], set[NT];
    __shared__ float sll[8];
    __shared__ float pbuf[8][2][32];    // per-warp double-buffered alpha vector

    const int tid = threadIdx.x;
    // vectorized prologue table loads
    {
        float4*       d1 = reinterpret_cast<float4*>(stab);
        const float4* s1 = reinterpret_cast<const float4*>(g_tab);
        float4*       d2 = reinterpret_cast<float4*>(setab);
        const float4* s2 = reinterpret_cast<const float4*>(g_etab);
        for (int i = tid; i < (NV * NT) / 4; i += 256) { d1[i] = s1[i]; d2[i] = s2[i]; }
        for (int i = tid; i < NV / 4; i += 256)
            reinterpret_cast<float4*>(sroff)[i] = reinterpret_cast<const float4*>(g_roff)[i];
        for (int i = tid; i < (NT * NT) / 4; i += 256)
            reinterpret_cast<float4*>(strans)[i] = reinterpret_cast<const float4*>(trans)[i];
        if (tid < NT) { sst[tid] = st[tid]; set[tid] = et[tid]; }
        const int4* sq = reinterpret_cast<const int4*>(seqs + blockIdx.x * 8 * NS);
        for (int i = tid; i < (8 * NS) / 4; i += 256)
            reinterpret_cast<int4*>(&sseq[0][0])[i] = sq[i];
    }
    __syncthreads();

    const int warp = tid >> 5;
    const int lane = tid & 31;
    const int b    = blockIdx.x * 8 + warp;
    const int* lab = labs + b * NS;
    const int* seq = sseq[warp];
    const int  t   = lane;
    const bool act = (t < NT);
    const int  tc  = act ? t : 0;      // clamped index for table reads

    // exp(transitions) column for this lane (one-time MUFU cost)
    float Ecol[NT];
#pragma unroll
    for (int p = 0; p < NT; p++) Ecol[p] = act ? __expf(strans[p * NT + tc]) : 0.0f;

    // numerator (gold path) + row-offset sum, lanes stride over s
    float nacc = 0.0f, racc = 0.0f;
    for (int s = lane; s < NS; s += 32) {
        int sv = seq[s], ls = lab[s];
        nacc += stab[sv * NT + ls];
        racc += sroff[sv];
        if (s + 1 < NS) nacc += strans[ls * NT + lab[s + 1]];
    }
#pragma unroll
    for (int o = 16; o; o >>= 1) {
        nacc += __shfl_xor_sync(0xffffffffu, nacc, o);
        racc += __shfl_xor_sync(0xffffffffu, racc, o);
    }

    // scaled forward scan: p[t] tracks exp(alpha - (roff-sum + c))
    float p = act ? __expf(sst[tc]) * setab[seq[0] * NT + tc] : 0.0f;
    float c = 0.0f;
    pbuf[warp][0][lane] = p;
    __syncwarp();

    // one forward step: read alpha vector from buffer rb, write new p to wb
    auto step = [&](int s, int rb, int wb) {
        const float4* pb = reinterpret_cast<const float4*>(pbuf[warp][rb]);
        float4 v0 = pb[0], v1 = pb[1], v2 = pb[2], v3 = pb[3], v4 = pb[4], v5 = pb[5];
        int sv = seq[s];
        float a0, a1, a2, a3;
        a0 = v0.x * Ecol[0];  a1 = v0.y * Ecol[1];  a2 = v0.z * Ecol[2];  a3 = v0.w * Ecol[3];
        a0 = fmaf(v1.x, Ecol[4],  a0); a1 = fmaf(v1.y, Ecol[5],  a1);
        a2 = fmaf(v1.z, Ecol[6],  a2); a3 = fmaf(v1.w, Ecol[7],  a3);
        a0 = fmaf(v2.x, Ecol[8],  a0); a1 = fmaf(v2.y, Ecol[9],  a1);
        a2 = fmaf(v2.z, Ecol[10], a2); a3 = fmaf(v2.w, Ecol[11], a3);
        a0 = fmaf(v3.x, Ecol[12], a0); a1 = fmaf(v3.y, Ecol[13], a1);
        a2 = fmaf(v3.z, Ecol[14], a2); a3 = fmaf(v3.w, Ecol[15], a3);
        a0 = fmaf(v4.x, Ecol[16], a0); a1 = fmaf(v4.y, Ecol[17], a1);
        a2 = fmaf(v4.z, Ecol[18], a2); a3 = fmaf(v4.w, Ecol[19], a3);
        a0 = fmaf(v5.x, Ecol[20], a0); a1 = fmaf(v5.y, Ecol[21], a1);
        a2 = fmaf(v5.z, Ecol[22], a2); a3 = fmaf(v5.w, Ecol[23], a3);
        float q = (a0 + a1) + (a2 + a3);
        float e = act ? setab[sv * NT + tc] : 0.0f;
        p = q * e;
        if ((s & 7) == 0) {                 // renormalize every 8 steps
            float s0 = ((v0.x + v0.y) + (v0.z + v0.w)) + ((v1.x + v1.y) + (v1.z + v1.w));
            float s1 = ((v2.x + v2.y) + (v2.z + v2.w)) + ((v3.x + v3.y) + (v3.z + v3.w));
            float s2 = ((v4.x + v4.y) + (v4.z + v4.w)) + ((v5.x + v5.y) + (v5.z + v5.w));
            float ssum = s0 + s1 + s2;
            p *= __fdividef(1.0f, ssum);
            c += __logf(ssum);
        }
        pbuf[warp][wb][lane] = p;
        __syncwarp();
    };

#pragma unroll 1
    for (int s = 1; s <= NS - 2; s += 2) {
        step(s,     0, 1);
        step(s + 1, 1, 0);
    }
    step(NS - 1, 0, 1);

    // denom = c + sum(roff over tokens) + log( sum_t p[t]*exp(end[t]) )
    float ee = act ? __expf(set[tc]) : 0.0f;
    float v = p * ee;
#pragma unroll
    for (int o = 16; o; o >>= 1) v += __shfl_xor_sync(0xffffffffu, v, o);
    float denom = c + racc + __logf(v);

    if (lane == 0) {
        float num = nacc + sst[lab[0]] + set[lab[NS - 1]];
        sll[warp] = num - denom;
    }
    __syncthreads();

    // fused deterministic reduce: int64 fixed-point atomics + last-block write
    if (tid == 0) {
        float bs = 0.0f;
#pragma unroll
        for (int w = 0; w < 8; w++) bs += sll[w];
        long long q = __float2ll_rn(bs * FPSCALE);
        atomicAdd(&g_acc, (unsigned long long)q);
        __threadfence();
        unsigned int done = atomicAdd(&g_ticket, 1u);
        if (done == gridDim.x - 1) {
            unsigned long long tot = atomicAdd(&g_acc, 0ULL);   // safe read
            double mean = (double)(long long)tot / ((double)FPSCALE * (double)NB);
            out[0] = (float)(-mean);
        }
    }
}

// ---------------------------------------------------------------------------
extern "C" void kernel_launch(void* const* d_in, const int* in_sizes, int n_in,
                              void* d_out, int out_size) {
    const int*   sequences   = (const int*)  d_in[0];
    const int*   labels      = (const int*)  d_in[1];
    // d_in[2] = true_lengths (unused by the reference forward)
    const float* emb         = (const float*)d_in[3];
    const float* w1          = (const float*)d_in[4];
    const float* b1          = (const float*)d_in[5];
    const float* w2          = (const float*)d_in[6];
    const float* b2          = (const float*)d_in[7];
    const float* start_trans = (const float*)d_in[8];
    const float* end_trans   = (const float*)d_in[9];
    const float* transitions = (const float*)d_in[10];
    float* out = (float*)d_out;

    k_transpose<<<dim3(16, 16), dim3(32, 8)>>>(w1);
    k_hidden<<<dim3(NV / 8, KC), 128>>>(emb);
    k_scores<<<NV, NT * 32>>>(b1, w2, b2);
    k_crf<<<NB / 8, 256>>>(sequences, labels, start_trans, end_trans, transitions, out);
}